// round 3
// baseline (speedup 1.0000x reference)
#include <cuda_runtime.h>
#include <math.h>

// ---------------------------------------------------------------------------
// SindyLayer: replicate jax.experimental.ode.odeint (dopri5, rtol=atol=1e-3)
// for dy/dt = iAy split into (u,v): du/dt = -A v, dv/dt = A u, A sym 64x64.
// Output: u (real part) at t = 1..128, shape [4096, 128, 64] f32.
//
// One persistent launch; 128 blocks x 256 threads; 32 rows/block; state in
// SMEM. GLOBAL adaptive step controller (grid barrier + deterministic global
// reduction) so every block follows the exact same step sequence as JAX's
// single global dopri5 controller.
// ---------------------------------------------------------------------------

#define HID      64
#define RPB      32
#define NTH      256
#define NBLK     128
#define FORECAST 128
#define ARR      2048            // floats per (u or v) array per block
#define YSZ      4096            // u+v
#define APITCH   68

// smem layout (floats)
#define OFF_A 0
#define OFF_Y (64*APITCH)              // two parity y buffers [u|v]
#define OFF_K (OFF_Y + 2*YSZ)          // k0..k6, each [u|v]
#define OFF_P (OFF_K + 7*YSZ)          // interp a,b,c,d,e (u only)
#define OFF_R (OFF_P + 5*ARR)          // reduction scratch
#define SM_FLOATS (OFF_R + 16)
#define SMEM_BYTES (SM_FLOATS*4)       // 205,888 B

typedef unsigned long long u64;

// ---- global controller state ----
__device__ float    g_red[2][2*NBLK];  // double-buffered partial sums
__device__ unsigned g_count;           // barrier counter (reset each launch)

// Dopri5 tableau exactly as in jax/experimental/ode.py
__constant__ float BETA[6][6] = {
  {(float)(1.0/5.0), 0.f, 0.f, 0.f, 0.f, 0.f},
  {(float)(3.0/40.0), (float)(9.0/40.0), 0.f, 0.f, 0.f, 0.f},
  {(float)(44.0/45.0), (float)(-56.0/15.0), (float)(32.0/9.0), 0.f, 0.f, 0.f},
  {(float)(19372.0/6561.0), (float)(-25360.0/2187.0), (float)(64448.0/6561.0),
   (float)(-212.0/729.0), 0.f, 0.f},
  {(float)(9017.0/3168.0), (float)(-355.0/33.0), (float)(46732.0/5247.0),
   (float)(49.0/176.0), (float)(-5103.0/18656.0), 0.f},
  {(float)(35.0/384.0), 0.f, (float)(500.0/1113.0), (float)(125.0/192.0),
   (float)(-2187.0/6784.0), (float)(11.0/84.0)}
};

// ---- packed f32x2 helpers (FFMA2 path) ----
__device__ __forceinline__ void ffma2(u64& d, u64 a, u64 b) {
  asm("fma.rn.f32x2 %0, %1, %2, %0;" : "+l"(d) : "l"(a), "l"(b));
}
__device__ __forceinline__ u64 ffma2o(u64 a, u64 b, u64 c) {
  u64 d;
  asm("fma.rn.f32x2 %0, %1, %2, %3;" : "=l"(d) : "l"(a), "l"(b), "l"(c));
  return d;
}
__device__ __forceinline__ u64 pack2(float x, float y) {
  u64 r; unsigned xi = __float_as_uint(x), yi = __float_as_uint(y);
  asm("mov.b64 %0, {%1, %2};" : "=l"(r) : "r"(xi), "r"(yi));
  return r;
}
__device__ __forceinline__ float2 unpack2(u64 v) {
  unsigned lo, hi;
  asm("mov.b64 {%0, %1}, %2;" : "=r"(lo), "=r"(hi) : "l"(v));
  return make_float2(__uint_as_float(lo), __uint_as_float(hi));
}

// Deterministic block-wide sum; result uniform across all 256 threads.
__device__ __forceinline__ float block_sum(float v, float* red) {
  __syncthreads();
  #pragma unroll
  for (int o = 16; o; o >>= 1) v += __shfl_down_sync(0xffffffffu, v, o);
  if ((threadIdx.x & 31) == 0) red[threadIdx.x >> 5] = v;
  __syncthreads();
  float s = red[0];
  #pragma unroll
  for (int w = 1; w < NTH/32; w++) s += red[w];
  return s;
}

// Grid barrier: monotonic counter; all 128 CTAs co-resident (1 CTA/SM).
__device__ __forceinline__ void gbar(unsigned& rnd) {
  __syncthreads();
  if (threadIdx.x == 0) {
    __threadfence();
    atomicAdd(&g_count, 1u);
    rnd += NBLK;
    volatile unsigned* vc = &g_count;
    while (*vc < rnd) __nanosleep(64);
    __threadfence();
  }
  __syncthreads();
}

// Global deterministic sum of up to two per-block values in one barrier round.
// Every block redundantly sums the 128 partials in fixed order 0..127 ->
// bitwise-identical result in every block. __ldcg bypasses (possibly stale) L1.
__device__ __forceinline__ void global_sum2(float v0, float v1, bool two,
                                            float* red, unsigned& rnd,
                                            int parity, float& s0, float& s1) {
  float b0 = block_sum(v0, red);
  float b1 = two ? block_sum(v1, red) : 0.f;
  if (threadIdx.x == 0) {
    g_red[parity][blockIdx.x] = b0;
    if (two) g_red[parity][NBLK + blockIdx.x] = b1;
  }
  gbar(rnd);
  float a0 = 0.f, a1 = 0.f;
  for (int b = 0; b < NBLK; b++) {
    a0 += __ldcg(&g_red[parity][b]);
    if (two) a1 += __ldcg(&g_red[parity][NBLK + b]);
  }
  s0 = a0; s1 = a1;
}

// RHS: k_u = -(v @ A^T), k_v = (u @ A^T). Thread owns column c, 8 rows.
__device__ __forceinline__ void rhs_eval(const float* __restrict__ y,
                                         float* __restrict__ kd,
                                         const u64* __restrict__ Areg,
                                         int c, int rbase)
{
  const float* yu = y;
  const float* yv = y + ARR;
  u64 aU[8], aV[8];
  #pragma unroll
  for (int i = 0; i < 8; i++) { aU[i] = 0ull; aV[i] = 0ull; }
  #pragma unroll
  for (int kp = 0; kp < 16; kp++) {
    u64 a0 = Areg[2*kp], a1 = Areg[2*kp+1];
    #pragma unroll
    for (int i = 0; i < 8; i++) {
      const int off = (rbase + i)*HID + kp*4;
      ulonglong2 v2 = *(const ulonglong2*)(yv + off);
      ulonglong2 u2 = *(const ulonglong2*)(yu + off);
      ffma2(aU[i], a0, v2.x); ffma2(aU[i], a1, v2.y);
      ffma2(aV[i], a0, u2.x); ffma2(aV[i], a1, u2.y);
    }
  }
  #pragma unroll
  for (int i = 0; i < 8; i++) {
    float2 su = unpack2(aU[i]);
    float2 sv = unpack2(aV[i]);
    kd[(rbase+i)*HID + c]       = -(su.x + su.y);
    kd[ARR + (rbase+i)*HID + c] =  (sv.x + sv.y);
  }
}

__global__ void reset_kernel() { g_count = 0u; }

__global__ void __launch_bounds__(NTH, 1)
sindy_kernel(const float* __restrict__ x,
             const float* __restrict__ tri,
             float* __restrict__ out)
{
  extern __shared__ float sm[];
  const int tid   = threadIdx.x;
  const int c     = tid & 63;
  const int rbase = (tid >> 6) * 8;
  const int brow  = blockIdx.x * RPB;

  float* Asm = sm + OFF_A;
  float* K   = sm + OFF_K;
  float* P   = sm + OFF_P;
  float* RED = sm + OFF_R;

  unsigned rnd = 0;     // barrier round target
  int gp = 0;           // reduction buffer parity

  const float CE0 = (float)(35.0/384.0 - 1951.0/21600.0);
  const float CE2 = (float)(500.0/1113.0 - 22642.0/50085.0);
  const float CE3 = (float)(125.0/192.0 - 451.0/720.0);
  const float CE4 = (float)(-2187.0/6784.0 + 12231.0/42400.0);
  const float CE5 = (float)(11.0/84.0 - 649.0/6300.0);
  const float CE6 = (float)(-1.0/60.0);
  const float CM0 = (float)(6025192743.0/30085553152.0/2.0);
  const float CM2 = (float)(51252292925.0/65400821598.0/2.0);
  const float CM3 = (float)(-2691868925.0/45128329728.0/2.0);
  const float CM4 = (float)(187940372067.0/1594534317056.0/2.0);
  const float CM5 = (float)(-1776094331.0/19743644256.0/2.0);
  const float CM6 = (float)(11237099.0/235043384.0/2.0);

  // Build symmetric A from tril coefficients
  for (int idx = tid; idx < HID*HID; idx += NTH) {
    int r = idx >> 6, cc = idx & 63;
    int R = r > cc ? r : cc, C = r > cc ? cc : r;
    Asm[r*APITCH + cc] = tri[R*(R+1)/2 + C];
  }

  // y0 = (x, 0); emit output slice t=1 (== y0 per odeint semantics)
  {
    float* Y0 = sm + OFF_Y;
    #pragma unroll
    for (int q = 0; q < 2; q++) {
      int e4 = tid + q*256;
      float4 xv = ((const float4*)x)[brow*16 + e4];
      ((float4*)Y0)[e4]         = xv;
      ((float4*)(Y0 + ARR))[e4] = make_float4(0.f, 0.f, 0.f, 0.f);
      int e = e4*4; int r = e >> 6; int h = e & 63;
      *(float4*)(out + ((size_t)(brow + r)*FORECAST + 0)*HID + h) = xv;
    }
  }
  __syncthreads();

  // A row c -> registers as packed f32 pairs
  u64 Areg[32];
  #pragma unroll
  for (int i = 0; i < 32; i++)
    Areg[i] = *(const u64*)(Asm + c*APITCH + 2*i);

  int p = 0;
  float* ycur = sm + OFF_Y;
  float* yalt = sm + OFF_Y + YSZ;

  // f0 -> k0 (FSAL seed)
  rhs_eval(ycur, K, Areg, c, rbase);
  __syncthreads();

  // ---- initial_step_size (Hairer, order=4), GLOBAL norms ----
  float dt;
  {
    float s0 = 0.f, s1 = 0.f;
    #pragma unroll
    for (int q = 0; q < 4; q++) {
      int e4 = tid + q*256;
      float4 y4 = ((const float4*)ycur)[e4];
      float4 f4 = ((const float4*)K)[e4];
      float ys[4] = {y4.x, y4.y, y4.z, y4.w};
      float fs[4] = {f4.x, f4.y, f4.z, f4.w};
      #pragma unroll
      for (int m = 0; m < 4; m++) {
        float sc = 1e-3f + 1e-3f*fabsf(ys[m]);
        float a0 = ys[m]/sc, a1 = fs[m]/sc;
        s0 = fmaf(a0, a0, s0); s1 = fmaf(a1, a1, s1);
      }
    }
    float t0s, t1s;
    global_sum2(s0, s1, true, RED, rnd, gp, t0s, t1s); gp ^= 1;
    float d0 = sqrtf(t0s);
    float d1 = sqrtf(t1s);
    float h0 = (d0 < 1e-5f || d1 < 1e-5f) ? 1e-6f : 0.01f*d0/d1;
    #pragma unroll
    for (int q = 0; q < 4; q++) {
      int e4 = tid + q*256;
      float4 y4 = ((const float4*)ycur)[e4];
      float4 f4 = ((const float4*)K)[e4];
      float4 r4;
      r4.x = fmaf(h0, f4.x, y4.x); r4.y = fmaf(h0, f4.y, y4.y);
      r4.z = fmaf(h0, f4.z, y4.z); r4.w = fmaf(h0, f4.w, y4.w);
      ((float4*)yalt)[e4] = r4;
    }
    __syncthreads();
    rhs_eval(yalt, K + YSZ, Areg, c, rbase);        // f1 probe
    __syncthreads();
    float s2 = 0.f;
    #pragma unroll
    for (int q = 0; q < 4; q++) {
      int e4 = tid + q*256;
      float4 y4  = ((const float4*)ycur)[e4];
      float4 f0v = ((const float4*)K)[e4];
      float4 f1v = ((const float4*)(K + YSZ))[e4];
      float ys[4] = {y4.x, y4.y, y4.z, y4.w};
      float a0[4] = {f0v.x, f0v.y, f0v.z, f0v.w};
      float a1[4] = {f1v.x, f1v.y, f1v.z, f1v.w};
      #pragma unroll
      for (int m = 0; m < 4; m++) {
        float sc = 1e-3f + 1e-3f*fabsf(ys[m]);
        float d = (a1[m] - a0[m])/sc;
        s2 = fmaf(d, d, s2);
      }
    }
    float t2s, dum;
    global_sum2(s2, 0.f, false, RED, rnd, gp, t2s, dum); gp ^= 1;
    float d2 = sqrtf(t2s) / h0;
    float h1;
    if (d1 <= 1e-15f && d2 <= 1e-15f) h1 = fmaxf(1e-6f, h0*1e-3f);
    else                              h1 = powf(0.01f/fmaxf(d1, d2), 0.2f);
    dt = fminf(100.f*h0, h1);
  }

  float t = 1.f, last_t = 1.f;

  // ---- main scan over output targets ----
  for (int tgt = 2; tgt <= FORECAST; tgt++) {
    float tf = (float)tgt;
    int guard = 0;
    while (t < tf && dt > 0.f && guard < 100000) {
      guard++;
      ycur = sm + OFF_Y + p*YSZ;
      yalt = sm + OFF_Y + (p^1)*YSZ;
      u64 dt2 = pack2(dt, dt);

      // stages 1..6
      for (int s = 1; s <= 6; s++) {
        ulonglong2 acc[4];
        #pragma unroll
        for (int q = 0; q < 4; q++) { acc[q].x = 0ull; acc[q].y = 0ull; }
        for (int j = 0; j < s; j++) {
          float bj = BETA[s-1][j];
          u64 b2 = pack2(bj, bj);
          #pragma unroll
          for (int q = 0; q < 4; q++) {
            ulonglong2 k2 = ((const ulonglong2*)(K + j*YSZ))[tid + q*256];
            ffma2(acc[q].x, b2, k2.x);
            ffma2(acc[q].y, b2, k2.y);
          }
        }
        #pragma unroll
        for (int q = 0; q < 4; q++) {
          ulonglong2 y2 = ((const ulonglong2*)ycur)[tid + q*256];
          ulonglong2 r2;
          r2.x = ffma2o(dt2, acc[q].x, y2.x);
          r2.y = ffma2o(dt2, acc[q].y, y2.y);
          ((ulonglong2*)yalt)[tid + q*256] = r2;
        }
        __syncthreads();
        rhs_eval(yalt, K + s*YSZ, Areg, c, rbase);
        __syncthreads();
      }
      // yalt == y1 (FSAL)

      // error ratio partial
      float ss = 0.f;
      #pragma unroll
      for (int q = 0; q < 4; q++) {
        int e4 = tid + q*256;
        float4 k0 = ((const float4*)K)[e4];
        float4 k2 = ((const float4*)(K + 2*YSZ))[e4];
        float4 k3 = ((const float4*)(K + 3*YSZ))[e4];
        float4 k4 = ((const float4*)(K + 4*YSZ))[e4];
        float4 k5 = ((const float4*)(K + 5*YSZ))[e4];
        float4 k6 = ((const float4*)(K + 6*YSZ))[e4];
        float4 y0v = ((const float4*)ycur)[e4];
        float4 y1v = ((const float4*)yalt)[e4];
        #define ECOMP(W) { \
          float er_ = dt*(CE0*k0.W + CE2*k2.W + CE3*k3.W + CE4*k4.W + CE5*k5.W + CE6*k6.W); \
          float tol_ = 1e-3f + 1e-3f*fmaxf(fabsf(y0v.W), fabsf(y1v.W)); \
          float rr_ = er_/tol_; ss = fmaf(rr_, rr_, ss); }
        ECOMP(x) ECOMP(y) ECOMP(z) ECOMP(w)
        #undef ECOMP
      }
      float tss, dum;
      global_sum2(ss, 0.f, false, RED, rnd, gp, tss, dum); gp ^= 1;
      float ratio  = sqrtf(tss * (1.f/524288.f));   // mean over full global state
      float er     = fmaxf(ratio, 1e-10f);
      float dfac   = (ratio < 1.f) ? 1.f : 0.2f;
      float factor = fminf(10.f, fmaxf(0.9f*powf(er, -0.2f), dfac));
      bool  accept = (ratio <= 1.f);

      if (accept) {
        // interpolation coefficients (u components only)
        #pragma unroll
        for (int q = 0; q < 2; q++) {
          int e4 = tid + q*256;
          float4 k0 = ((const float4*)K)[e4];
          float4 k2 = ((const float4*)(K + 2*YSZ))[e4];
          float4 k3 = ((const float4*)(K + 3*YSZ))[e4];
          float4 k4 = ((const float4*)(K + 4*YSZ))[e4];
          float4 k5 = ((const float4*)(K + 5*YSZ))[e4];
          float4 k6 = ((const float4*)(K + 6*YSZ))[e4];
          float4 y0v = ((const float4*)ycur)[e4];
          float4 y1v = ((const float4*)yalt)[e4];
          float4 A4, B4, C4, D4, E4;
          #define ICOMP(W) { \
            float ym = fmaf(dt, CM0*k0.W + CM2*k2.W + CM3*k3.W + CM4*k4.W + CM5*k5.W + CM6*k6.W, y0v.W); \
            float D0 = dt*k0.W, D1 = dt*k6.W; \
            A4.W = -2.f*D0 + 2.f*D1 -  8.f*y0v.W -  8.f*y1v.W + 16.f*ym; \
            B4.W =  5.f*D0 - 3.f*D1 + 18.f*y0v.W + 14.f*y1v.W - 32.f*ym; \
            C4.W = -4.f*D0 +     D1 - 11.f*y0v.W -  5.f*y1v.W + 16.f*ym; \
            D4.W = D0; E4.W = y0v.W; }
          ICOMP(x) ICOMP(y) ICOMP(z) ICOMP(w)
          #undef ICOMP
          ((float4*)(P))[e4]         = A4;
          ((float4*)(P +   ARR))[e4] = B4;
          ((float4*)(P + 2*ARR))[e4] = C4;
          ((float4*)(P + 3*ARR))[e4] = D4;
          ((float4*)(P + 4*ARR))[e4] = E4;
        }
        // FSAL: k0 <- k6
        #pragma unroll
        for (int q = 0; q < 4; q++) {
          int e4 = tid + q*256;
          ((float4*)K)[e4] = ((const float4*)(K + 6*YSZ))[e4];
        }
        last_t = t; t = t + dt; p ^= 1;
      }
      dt = dt * factor;
      __syncthreads();
    }

    // evaluate interpolation polynomial at the target and store
    float xr = (tf - last_t) / (t - last_t);
    #pragma unroll
    for (int q = 0; q < 2; q++) {
      int e4 = tid + q*256;
      float4 A4 = ((const float4*)P)[e4];
      float4 B4 = ((const float4*)(P +   ARR))[e4];
      float4 C4 = ((const float4*)(P + 2*ARR))[e4];
      float4 D4 = ((const float4*)(P + 3*ARR))[e4];
      float4 E4 = ((const float4*)(P + 4*ARR))[e4];
      float4 o;
      o.x = fmaf(fmaf(fmaf(fmaf(A4.x, xr, B4.x), xr, C4.x), xr, D4.x), xr, E4.x);
      o.y = fmaf(fmaf(fmaf(fmaf(A4.y, xr, B4.y), xr, C4.y), xr, D4.y), xr, E4.y);
      o.z = fmaf(fmaf(fmaf(fmaf(A4.z, xr, B4.z), xr, C4.z), xr, D4.z), xr, E4.z);
      o.w = fmaf(fmaf(fmaf(fmaf(A4.w, xr, B4.w), xr, C4.w), xr, D4.w), xr, E4.w);
      int e = e4*4; int r = e >> 6; int h = e & 63;
      *(float4*)(out + ((size_t)(brow + r)*FORECAST + (tgt - 1))*HID + h) = o;
    }
  }
}

extern "C" void kernel_launch(void* const* d_in, const int* in_sizes, int n_in,
                              void* d_out, int out_size) {
  (void)in_sizes; (void)n_in; (void)out_size;
  const float* x   = (const float*)d_in[0];
  const float* tri = (const float*)d_in[1];
  float* out = (float*)d_out;
  cudaFuncSetAttribute(sindy_kernel,
                       cudaFuncAttributeMaxDynamicSharedMemorySize, SMEM_BYTES);
  reset_kernel<<<1, 1>>>();
  sindy_kernel<<<NBLK, NTH, SMEM_BYTES>>>(x, tri, out);
}